// round 1
// baseline (speedup 1.0000x reference)
#include <cuda_runtime.h>
#include <math.h>

#define NPC 16384
#define NTC 131072
#define NFC 131072
#define EC  262144
#define BC  256

// ---------------- device scratch (no cudaMalloc allowed) ----------------
__device__ float g_xp[2 * NPC * 64];
__device__ float g_xt[2 * NTC * 64];
__device__ float g_xf[2 * NFC * 64];
__device__ float g_hsp0[NPC * 64];   // hs for pt (src=p)
__device__ float g_hsp1[NPC * 64];   // hs for pf (src=p)
__device__ float g_hst[NTC * 64];    // hs for tp (src=t)
__device__ float g_hsf[NFC * 64];    // hs for fp (src=f)
__device__ float g_ss_pt[NPC], g_ss_pf[NPC];
__device__ float g_ss_tp[NTC], g_ss_fp[NFC];
__device__ float g_sd_pt[NTC], g_sd_pf[NFC];
__device__ float g_sd_tp[NPC], g_sd_fp[NPC];
__device__ float g_wsv[4 * 64], g_wdv[4 * 64];
__device__ int g_rp_pt[NTC + 1], g_rp_pf[NFC + 1];
__device__ int g_rp_tp[NPC + 1], g_rp_fp[NPC + 1];
__device__ int g_cs_pt[EC], g_cs_tp[EC], g_cs_pf[EC], g_cs_fp[EC];
__device__ int g_tmp[NTC];
__device__ float g_ap[NPC * 64];
__device__ float g_ra[NPC * 2];
__device__ float g_rep[BC * 576];
__device__ float g_h1[BC * 64], g_h2[BC * 64];

#define FULLMASK 0xffffffffu

// ---------------- CSR build ----------------
__global__ void zero_i(int* p, int n) {
    int i = blockIdx.x * blockDim.x + threadIdx.x;
    if (i < n) p[i] = 0;
}

__global__ void hist_k(const int* __restrict__ dst, int* __restrict__ deg, int n) {
    int i = blockIdx.x * blockDim.x + threadIdx.x;
    if (i < n) atomicAdd(&deg[dst[i]], 1);
}

__global__ void scan_excl(const int* __restrict__ deg, int* __restrict__ rowptr, int n) {
    __shared__ int warp_sums[32];
    __shared__ int s_carry;
    int tid = threadIdx.x;          // 1024 threads
    int lane = tid & 31, wid = tid >> 5;
    if (tid == 0) s_carry = 0;
    __syncthreads();
    for (int base = 0; base < n; base += 1024) {
        int i = base + tid;
        int v = (i < n) ? deg[i] : 0;
        int x = v;
        #pragma unroll
        for (int off = 1; off < 32; off <<= 1) {
            int y = __shfl_up_sync(FULLMASK, x, off);
            if (lane >= off) x += y;
        }
        if (lane == 31) warp_sums[wid] = x;
        __syncthreads();
        if (tid < 32) {
            int s = warp_sums[tid];
            #pragma unroll
            for (int off = 1; off < 32; off <<= 1) {
                int y = __shfl_up_sync(FULLMASK, s, off);
                if (tid >= off) s += y;
            }
            warp_sums[tid] = s;
        }
        __syncthreads();
        int incl = x + (wid ? warp_sums[wid - 1] : 0);
        if (i < n) rowptr[i] = s_carry + incl - v;
        int chunk_total = warp_sums[31];
        __syncthreads();
        if (tid == 0) s_carry += chunk_total;
        __syncthreads();
    }
    if (tid == 0) rowptr[n] = s_carry;
}

__global__ void scatter_k(const int* __restrict__ src, const int* __restrict__ dst,
                          const int* __restrict__ rowptr, int* __restrict__ cur,
                          int* __restrict__ csr_src, int n) {
    int i = blockIdx.x * blockDim.x + threadIdx.x;
    if (i >= n) return;
    int d = dst[i];
    int pos = rowptr[d] + atomicAdd(&cur[d], 1);
    csr_src[pos] = src[i];
}

// ---------------- embed ----------------
__global__ void embed_k(const float* __restrict__ mass, const int* __restrict__ pstate,
                        const float* __restrict__ embW, const float* __restrict__ embS,
                        float* __restrict__ xp) {
    int idx = blockIdx.x * blockDim.x + threadIdx.x;
    if (idx >= NPC * 64) return;
    int n = idx >> 6, j = idx & 63;
    float v;
    if (j < 32) v = mass[n] * embW[j];
    else {
        int st = pstate[2 * n] + 2 * pstate[2 * n + 1];
        v = embS[st * 32 + (j - 32)];
    }
    xp[idx] = v;
}

// ---------------- per-layer score vectors: wsv[t] = Ws[l,t] @ a_s[l,t] ----------------
__global__ void vec_wsd(const float* __restrict__ Ws, const float* __restrict__ as,
                        const float* __restrict__ Wd, const float* __restrict__ ad,
                        float* __restrict__ wsv, float* __restrict__ wdv) {
    int tid = threadIdx.x;              // 512
    int which = tid >> 8;
    int t = (tid >> 6) & 3, i = tid & 63;
    const float* W = which ? Wd : Ws;
    const float* a = which ? ad : as;
    float* o = which ? wdv : wsv;
    float acc = 0.f;
    const float* wr = W + (t * 64 + i) * 64;
    const float* ar = a + t * 64;
    #pragma unroll 8
    for (int j = 0; j < 64; j++) acc = fmaf(wr[j], ar[j], acc);
    o[t * 64 + i] = acc;
}

// ---------------- 64x64 matmul: Y[N,64] = X[N,64] @ W[64,64] ----------------
__global__ void mm64(const float* __restrict__ X, const float* __restrict__ W,
                     float* __restrict__ Y, int N) {
    __shared__ float Xs[64][65];
    __shared__ float Wsh[64][68];
    int row0 = blockIdx.x * 64;
    int tid = threadIdx.x;      // 256
    const float4* W4 = (const float4*)W;
    for (int i = tid; i < 1024; i += 256) {
        float4 v = W4[i];
        int r = i >> 4, c = (i & 15) * 4;
        Wsh[r][c] = v.x; Wsh[r][c + 1] = v.y; Wsh[r][c + 2] = v.z; Wsh[r][c + 3] = v.w;
    }
    const float4* X4 = (const float4*)(X + (size_t)row0 * 64);
    for (int i = tid; i < 1024; i += 256) {
        float4 v = X4[i];
        int r = i >> 4, c = (i & 15) * 4;
        Xs[r][c] = v.x; Xs[r][c + 1] = v.y; Xs[r][c + 2] = v.z; Xs[r][c + 3] = v.w;
    }
    __syncthreads();
    int tx = tid & 15, ty = tid >> 4;
    int c0 = tx * 4, r0 = ty * 4;
    float acc[4][4] = {};
    #pragma unroll
    for (int k = 0; k < 64; k++) {
        float4 w = *(const float4*)&Wsh[k][c0];
        float x0 = Xs[r0][k], x1 = Xs[r0 + 1][k], x2 = Xs[r0 + 2][k], x3 = Xs[r0 + 3][k];
        acc[0][0] = fmaf(x0, w.x, acc[0][0]); acc[0][1] = fmaf(x0, w.y, acc[0][1]);
        acc[0][2] = fmaf(x0, w.z, acc[0][2]); acc[0][3] = fmaf(x0, w.w, acc[0][3]);
        acc[1][0] = fmaf(x1, w.x, acc[1][0]); acc[1][1] = fmaf(x1, w.y, acc[1][1]);
        acc[1][2] = fmaf(x1, w.z, acc[1][2]); acc[1][3] = fmaf(x1, w.w, acc[1][3]);
        acc[2][0] = fmaf(x2, w.x, acc[2][0]); acc[2][1] = fmaf(x2, w.y, acc[2][1]);
        acc[2][2] = fmaf(x2, w.z, acc[2][2]); acc[2][3] = fmaf(x2, w.w, acc[2][3]);
        acc[3][0] = fmaf(x3, w.x, acc[3][0]); acc[3][1] = fmaf(x3, w.y, acc[3][1]);
        acc[3][2] = fmaf(x3, w.z, acc[3][2]); acc[3][3] = fmaf(x3, w.w, acc[3][3]);
    }
    #pragma unroll
    for (int i = 0; i < 4; i++) {
        float4 o = make_float4(acc[i][0], acc[i][1], acc[i][2], acc[i][3]);
        *(float4*)&Y[((size_t)(row0 + r0 + i)) * 64 + c0] = o;
    }
}

// ---------------- up to 4 per-row dot products against fixed 64-vectors ----------------
__global__ void dot4(const float* __restrict__ X, int n,
                     const float* v0, float* o0, const float* v1, float* o1,
                     const float* v2, float* o2, const float* v3, float* o3) {
    int idx = blockIdx.x * blockDim.x + threadIdx.x;
    int w = idx >> 5;
    if (w >= n) return;
    int lane = idx & 31;
    float2 x = *(const float2*)&X[(size_t)w * 64 + lane * 2];
#define DODOT(v, o) if (v) { \
        float s = x.x * v[2 * lane] + x.y * v[2 * lane + 1]; \
        for (int off = 16; off; off >>= 1) s += __shfl_xor_sync(FULLMASK, s, off); \
        if (lane == 0) o[w] = s; }
    DODOT(v0, o0)
    DODOT(v1, o1)
    DODOT(v2, o2)
    DODOT(v3, o3)
#undef DODOT
}

// ---------------- GAT aggregation: warp per dst node, up to 2 edge lists ----------------
__device__ __forceinline__ void agg_list(int w, int lane,
                                         const int* __restrict__ rp, const int* __restrict__ cs,
                                         const float* __restrict__ ss, const float* __restrict__ sd,
                                         const float* __restrict__ hs,
                                         float& ax, float& ay) {
    int beg = rp[w], end = rp[w + 1];
    if (end <= beg) return;
    float sdv = sd[w];
    float m = -1e30f;
    for (int j = beg + lane; j < end; j += 32) {
        float e = ss[cs[j]] + sdv;
        e = e > 0.f ? e : 0.2f * e;
        m = fmaxf(m, e);
    }
    for (int o = 16; o; o >>= 1) m = fmaxf(m, __shfl_xor_sync(FULLMASK, m, o));
    float s = 0.f;
    for (int j = beg + lane; j < end; j += 32) {
        float e = ss[cs[j]] + sdv;
        e = e > 0.f ? e : 0.2f * e;
        s += expf(e - m);
    }
    for (int o = 16; o; o >>= 1) s += __shfl_xor_sync(FULLMASK, s, o);
    float inv = 1.f / s;
    for (int j = beg; j < end; j++) {
        int src = cs[j];
        float e = ss[src] + sdv;
        e = e > 0.f ? e : 0.2f * e;
        float wt = expf(e - m) * inv;
        float2 h = *(const float2*)&hs[(size_t)src * 64 + lane * 2];
        ax = fmaf(wt, h.x, ax);
        ay = fmaf(wt, h.y, ay);
    }
}

__global__ void agg_kernel(const int* rp0, const int* cs0, const float* ss0, const float* sd0,
                           const float* hs0, const float* b0,
                           const int* rp1, const int* cs1, const float* ss1, const float* sd1,
                           const float* hs1, const float* b1,
                           float* __restrict__ out, int n, int relu) {
    int idx = blockIdx.x * blockDim.x + threadIdx.x;
    int w = idx >> 5;
    if (w >= n) return;
    int lane = idx & 31;
    float ax = b0[2 * lane], ay = b0[2 * lane + 1];
    if (b1) { ax += b1[2 * lane]; ay += b1[2 * lane + 1]; }
    agg_list(w, lane, rp0, cs0, ss0, sd0, hs0, ax, ay);
    if (rp1) agg_list(w, lane, rp1, cs1, ss1, sd1, hs1, ax, ay);
    if (relu) { ax = fmaxf(ax, 0.f); ay = fmaxf(ay, 0.f); }
    *(float2*)&out[(size_t)w * 64 + lane * 2] = make_float2(ax, ay);
}

// ---------------- pooling: max|min|mean per graph per dim ----------------
__global__ void pool_k(const float* __restrict__ x, int npg, float* __restrict__ rep, int off) {
    int b = blockIdx.x;
    int t = threadIdx.x;            // 256
    int d = t & 63, c = t >> 6;
    const float* base = x + (size_t)b * npg * 64;
    float mx = -1e30f, mn = 1e30f, sm = 0.f;
    for (int n = c; n < npg; n += 4) {
        float v = base[(size_t)n * 64 + d];
        mx = fmaxf(mx, v); mn = fminf(mn, v); sm += v;
    }
    __shared__ float smx[4][64], smn[4][64], ssm[4][64];
    smx[c][d] = mx; smn[c][d] = mn; ssm[c][d] = sm;
    __syncthreads();
    if (c == 0) {
        for (int i = 1; i < 4; i++) {
            mx = fmaxf(mx, smx[i][d]); mn = fminf(mn, smn[i][d]); sm += ssm[i][d];
        }
        rep[b * 576 + off + d] = mx;
        rep[b * 576 + off + 64 + d] = mn;
        rep[b * 576 + off + 128 + d] = sm / (float)npg;
    }
}

// ---------------- LayerNorm + out_a projection ----------------
__global__ void ln_ra(const float* __restrict__ ap, const float* __restrict__ g,
                      const float* __restrict__ be, const float* __restrict__ Wa,
                      const float* __restrict__ ba, float* __restrict__ ra) {
    int idx = blockIdx.x * blockDim.x + threadIdx.x;
    int n = idx >> 5;
    if (n >= NPC) return;
    int lane = idx & 31;
    float2 v = *(const float2*)&ap[(size_t)n * 64 + lane * 2];
    float sum = v.x + v.y;
    for (int o = 16; o; o >>= 1) sum += __shfl_xor_sync(FULLMASK, sum, o);
    float mu = sum * (1.f / 64.f);
    float dx = v.x - mu, dy = v.y - mu;
    float vs = dx * dx + dy * dy;
    for (int o = 16; o; o >>= 1) vs += __shfl_xor_sync(FULLMASK, vs, o);
    float rs = rsqrtf(vs * (1.f / 64.f) + 1e-5f);
    float y0 = dx * rs * g[2 * lane] + be[2 * lane];
    float y1 = dy * rs * g[2 * lane + 1] + be[2 * lane + 1];
    float r0 = y0 * Wa[(2 * lane) * 2]     + y1 * Wa[(2 * lane + 1) * 2];
    float r1 = y0 * Wa[(2 * lane) * 2 + 1] + y1 * Wa[(2 * lane + 1) * 2 + 1];
    for (int o = 16; o; o >>= 1) r0 += __shfl_xor_sync(FULLMASK, r0, o);
    for (int o = 16; o; o >>= 1) r1 += __shfl_xor_sync(FULLMASK, r1, o);
    if (lane == 0) {
        ra[2 * n]     = r0 + ba[0];
        ra[2 * n + 1] = r1 + ba[1];
    }
}

// ---------------- per-graph softmax + scatter to actions ----------------
__device__ __forceinline__ float blk64_max(float v, volatile float* sh) {
    for (int o = 16; o; o >>= 1) v = fmaxf(v, __shfl_xor_sync(FULLMASK, v, o));
    if ((threadIdx.x & 31) == 0) sh[threadIdx.x >> 5] = v;
    __syncthreads();
    float r = fmaxf(sh[0], sh[1]);
    __syncthreads();
    return r;
}
__device__ __forceinline__ float blk64_sum(float v, volatile float* sh) {
    for (int o = 16; o; o >>= 1) v += __shfl_xor_sync(FULLMASK, v, o);
    if ((threadIdx.x & 31) == 0) sh[threadIdx.x >> 5] = v;
    __syncthreads();
    float r = sh[0] + sh[1];
    __syncthreads();
    return r;
}

__global__ void act_softmax(const float* __restrict__ ra, const int* __restrict__ part_id,
                            float* __restrict__ out) {
    __shared__ float sh[2];
    int b = blockIdx.x, t = threadIdx.x;        // 64
    int n = b * 64 + t;
    float v0 = ra[2 * n], v1 = ra[2 * n + 1];
    float m0 = blk64_max(v0, sh);
    float m1 = blk64_max(v1, sh);
    float e0 = expf(v0 - m0), e1 = expf(v1 - m1);
    float s0 = blk64_sum(e0, sh);
    float s1 = blk64_sum(e1, sh);
    int p = part_id[n];
    out[b * 128 + p] = e0 / s0;
    out[b * 128 + 64 + p] = e1 / s1;
}

// ---------------- value head MLPs ----------------
__global__ void mlp_k(const float* __restrict__ in, int K, const float* __restrict__ W,
                      const float* __restrict__ bias, float* __restrict__ out) {
    __shared__ float s[576];
    int b = blockIdx.x, j = threadIdx.x;        // 64
    for (int k = j; k < K; k += 64) s[k] = in[b * K + k];
    __syncthreads();
    float acc = bias[j];
    for (int k = 0; k < K; k++) acc = fmaf(s[k], W[k * 64 + j], acc);
    acc = 0.5f * acc * (1.f + erff(acc * 0.70710678118654752f));
    out[b * 64 + j] = acc;
}

__global__ void mlp_out(const float* __restrict__ h, const float* __restrict__ Wo,
                        const float* __restrict__ bo, float* __restrict__ V) {
    int idx = blockIdx.x * blockDim.x + threadIdx.x;
    int b = idx >> 5;
    if (b >= BC) return;
    int lane = idx & 31;
    float2 v = *(const float2*)&h[b * 64 + lane * 2];
    float s = v.x * Wo[2 * lane] + v.y * Wo[2 * lane + 1];
    for (int o = 16; o; o >>= 1) s += __shfl_xor_sync(FULLMASK, s, o);
    if (lane == 0) V[b] = tanhf(s + bo[0]);
}

// ---------------- host ----------------
#define SYMF(p, s) do { void* _q; cudaGetSymbolAddress(&_q, s); p = (float*)_q; } while (0)
#define SYMI(p, s) do { void* _q; cudaGetSymbolAddress(&_q, s); p = (int*)_q; } while (0)

static void build_csr(const int* src, const int* dst, int n_dst, int* rowptr, int* csr_src, int* tmp) {
    int zb = (n_dst + 255) / 256;
    zero_i<<<zb, 256>>>(tmp, n_dst);
    hist_k<<<EC / 256, 256>>>(dst, tmp, EC);
    scan_excl<<<1, 1024>>>(tmp, rowptr, n_dst);
    zero_i<<<zb, 256>>>(tmp, n_dst);
    scatter_k<<<EC / 256, 256>>>(src, dst, rowptr, tmp, csr_src, EC);
}

extern "C" void kernel_launch(void* const* d_in, const int* in_sizes, int n_in,
                              void* d_out, int out_size) {
    const float* mass      = (const float*)d_in[0];
    const int*   pstate    = (const int*)d_in[1];
    const float* torque_x  = (const float*)d_in[2];
    const float* force_x   = (const float*)d_in[3];
    const int* e_pt_src = (const int*)d_in[4];
    const int* e_pt_dst = (const int*)d_in[5];
    const int* e_tp_src = (const int*)d_in[6];
    const int* e_tp_dst = (const int*)d_in[7];
    const int* e_pf_src = (const int*)d_in[8];
    const int* e_pf_dst = (const int*)d_in[9];
    const int* e_fp_src = (const int*)d_in[10];
    const int* e_fp_dst = (const int*)d_in[11];
    // const int* batch = (const int*)d_in[12];  // structure: node // 64
    const int* part_id  = (const int*)d_in[13];
    const float* embW   = (const float*)d_in[14];
    const float* embS   = (const float*)d_in[15];
    const float* W_src  = (const float*)d_in[16];
    const float* W_dst  = (const float*)d_in[17];
    const float* a_src  = (const float*)d_in[18];
    const float* a_dst  = (const float*)d_in[19];
    const float* b_conv = (const float*)d_in[20];
    const float* ln_g   = (const float*)d_in[21];
    const float* ln_b   = (const float*)d_in[22];
    const float* outaW  = (const float*)d_in[23];
    const float* outab  = (const float*)d_in[24];
    const float* innW   = (const float*)d_in[25];
    const float* innb   = (const float*)d_in[26];
    const float* fulW   = (const float*)d_in[27];
    const float* fulb   = (const float*)d_in[28];
    const float* outW   = (const float*)d_in[29];
    const float* outb   = (const float*)d_in[30];
    float* out = (float*)d_out;

    float *xp, *xt, *xf, *hsp0, *hsp1, *hst, *hsf;
    float *ss_pt, *ss_pf, *ss_tp, *ss_fp, *sd_pt, *sd_pf, *sd_tp, *sd_fp;
    float *wsv, *wdv, *ap, *ra, *rep, *h1, *h2;
    int *rp_pt, *rp_pf, *rp_tp, *rp_fp, *cs_pt, *cs_tp, *cs_pf, *cs_fp, *tmp;
    SYMF(xp, g_xp); SYMF(xt, g_xt); SYMF(xf, g_xf);
    SYMF(hsp0, g_hsp0); SYMF(hsp1, g_hsp1); SYMF(hst, g_hst); SYMF(hsf, g_hsf);
    SYMF(ss_pt, g_ss_pt); SYMF(ss_pf, g_ss_pf); SYMF(ss_tp, g_ss_tp); SYMF(ss_fp, g_ss_fp);
    SYMF(sd_pt, g_sd_pt); SYMF(sd_pf, g_sd_pf); SYMF(sd_tp, g_sd_tp); SYMF(sd_fp, g_sd_fp);
    SYMF(wsv, g_wsv); SYMF(wdv, g_wdv); SYMF(ap, g_ap); SYMF(ra, g_ra);
    SYMF(rep, g_rep); SYMF(h1, g_h1); SYMF(h2, g_h2);
    SYMI(rp_pt, g_rp_pt); SYMI(rp_pf, g_rp_pf); SYMI(rp_tp, g_rp_tp); SYMI(rp_fp, g_rp_fp);
    SYMI(cs_pt, g_cs_pt); SYMI(cs_tp, g_cs_tp); SYMI(cs_pf, g_cs_pf); SYMI(cs_fp, g_cs_fp);
    SYMI(tmp, g_tmp);

    // CSR per edge type (edges constant across layers)
    build_csr(e_pt_src, e_pt_dst, NTC, rp_pt, cs_pt, tmp);
    build_csr(e_tp_src, e_tp_dst, NPC, rp_tp, cs_tp, tmp);
    build_csr(e_pf_src, e_pf_dst, NFC, rp_pf, cs_pf, tmp);
    build_csr(e_fp_src, e_fp_dst, NPC, rp_fp, cs_fp, tmp);

    // initial embed -> xp buffer 0
    embed_k<<<(NPC * 64) / 256, 256>>>(mass, pstate, embW, embS, xp);

    for (int l = 0; l < 5; l++) {
        int pin = l & 1, pout = (l + 1) & 1;
        const float* xpi = xp + (size_t)pin * NPC * 64;
        const float* xti = (l == 0) ? torque_x : xt + (size_t)pin * NTC * 64;
        const float* xfi = (l == 0) ? force_x : xf + (size_t)pin * NFC * 64;
        float* xpo = xp + (size_t)pout * NPC * 64;
        float* xto = xt + (size_t)pout * NTC * 64;
        float* xfo = xf + (size_t)pout * NFC * 64;
        const float* Wl  = W_src + (size_t)l * 4 * 4096;
        const float* Wdl = W_dst + (size_t)l * 4 * 4096;
        const float* asl = a_src + (size_t)l * 4 * 64;
        const float* adl = a_dst + (size_t)l * 4 * 64;
        const float* bl  = b_conv + (size_t)l * 4 * 64;
        int relu = (l < 3) ? 1 : 0;
        int actor = (l == 4);

        vec_wsd<<<1, 512>>>(Wl, asl, Wdl, adl, wsv, wdv);

        // hs matmuls (src-side only)
        mm64<<<NTC / 64, 256>>>(xti, Wl + 1 * 4096, hst, NTC);   // tp (src=t)
        mm64<<<NFC / 64, 256>>>(xfi, Wl + 3 * 4096, hsf, NFC);   // fp (src=f)
        if (!actor) {
            mm64<<<NPC / 64, 256>>>(xpi, Wl + 0 * 4096, hsp0, NPC);  // pt
            mm64<<<NPC / 64, 256>>>(xpi, Wl + 2 * 4096, hsp1, NPC);  // pf
        }

        // attention scalar dots
        if (!actor) {
            dot4<<<(NPC * 32) / 256, 256>>>(xpi, NPC,
                 wsv + 0 * 64, ss_pt, wsv + 2 * 64, ss_pf,
                 wdv + 1 * 64, sd_tp, wdv + 3 * 64, sd_fp);
            dot4<<<(NTC * 32) / 256, 256>>>(xti, NTC,
                 wsv + 1 * 64, ss_tp, wdv + 0 * 64, sd_pt, nullptr, nullptr, nullptr, nullptr);
            dot4<<<(NFC * 32) / 256, 256>>>(xfi, NFC,
                 wsv + 3 * 64, ss_fp, wdv + 2 * 64, sd_pf, nullptr, nullptr, nullptr, nullptr);
        } else {
            dot4<<<(NPC * 32) / 256, 256>>>(xpi, NPC,
                 wdv + 1 * 64, sd_tp, wdv + 3 * 64, sd_fp, nullptr, nullptr, nullptr, nullptr);
            dot4<<<(NTC * 32) / 256, 256>>>(xti, NTC,
                 wsv + 1 * 64, ss_tp, nullptr, nullptr, nullptr, nullptr, nullptr, nullptr);
            dot4<<<(NFC * 32) / 256, 256>>>(xfi, NFC,
                 wsv + 3 * 64, ss_fp, nullptr, nullptr, nullptr, nullptr, nullptr, nullptr);
        }

        // aggregation
        if (!actor) {
            agg_kernel<<<(NTC * 32) / 256, 256>>>(rp_pt, cs_pt, ss_pt, sd_pt, hsp0, bl + 0 * 64,
                nullptr, nullptr, nullptr, nullptr, nullptr, nullptr, xto, NTC, relu);
            agg_kernel<<<(NFC * 32) / 256, 256>>>(rp_pf, cs_pf, ss_pf, sd_pf, hsp1, bl + 2 * 64,
                nullptr, nullptr, nullptr, nullptr, nullptr, nullptr, xfo, NFC, relu);
        }
        float* pdst = actor ? ap : xpo;
        agg_kernel<<<(NPC * 32) / 256, 256>>>(rp_tp, cs_tp, ss_tp, sd_tp, hst, bl + 1 * 64,
            rp_fp, cs_fp, ss_fp, sd_fp, hsf, bl + 3 * 64, pdst, NPC, actor ? 0 : relu);
    }

    // after layer 3 (l=3 writes buffer 0)
    const float* xp_fin = xp;
    const float* xt_fin = xt;
    const float* xf_fin = xf;
    pool_k<<<BC, 256>>>(xp_fin, 64, rep, 0);
    pool_k<<<BC, 256>>>(xt_fin, 512, rep, 192);
    pool_k<<<BC, 256>>>(xf_fin, 512, rep, 384);

    // actor head
    ln_ra<<<(NPC * 32) / 256, 256>>>(ap, ln_g, ln_b, outaW, outab, ra);
    act_softmax<<<BC, 64>>>(ra, part_id, out);

    // value head
    mlp_k<<<BC, 64>>>(rep, 576, innW, innb, h1);
    mlp_k<<<BC, 64>>>(h1, 64, fulW, fulb, h2);
    mlp_out<<<(BC * 32) / 256, 256>>>(h2, outW, outb, out + BC * 128);
}

// round 3
// speedup vs baseline: 1.1352x; 1.1352x over previous
#include <cuda_runtime.h>
#include <math.h>

#define NPC 16384
#define NTC 131072
#define NFC 131072
#define EC  262144
#define BC  256
#define FULLMASK 0xffffffffu

// ---------------- device scratch ----------------
__device__ float g_xp[NPC * 64];
__device__ float g_xt[NTC * 64];
__device__ float g_xf[NFC * 64];
__device__ float g_ap[NPC * 64];
__device__ float g_zt[NTC * 64];
__device__ float g_zf[NFC * 64];
__device__ float g_ztp[NPC * 64];
__device__ float g_zfp[NPC * 64];
__device__ float g_ss_pt[NPC], g_ss_pf[NPC], g_sd_tp[NPC], g_sd_fp[NPC];
__device__ float g_ss_tp[NTC], g_sd_pt[NTC];
__device__ float g_ss_fp[NFC], g_sd_pf[NFC];
__device__ float g_a_pt[EC], g_a_tp[EC], g_a_pf[EC], g_a_fp[EC];
__device__ float g_wsv[5 * 4 * 64], g_wdv[5 * 4 * 64];
__device__ int g_rp_pt[NTC + 1], g_rp_pf[NFC + 1];
__device__ int g_rp_tp[NPC + 1], g_rp_fp[NPC + 1];
__device__ int g_cs_pt[EC], g_cs_tp[EC], g_cs_pf[EC], g_cs_fp[EC];
__device__ int g_tmp[NTC];
__device__ float g_ra[NPC * 2];
__device__ float g_rep[BC * 576];
__device__ float g_h1[BC * 64], g_h2[BC * 64];

// ---------------- CSR build ----------------
__global__ void zero_i(int* p, int n) {
    int i = blockIdx.x * blockDim.x + threadIdx.x;
    if (i < n) p[i] = 0;
}

__global__ void hist_k(const int* __restrict__ dst, int* __restrict__ deg, int n) {
    int i = blockIdx.x * blockDim.x + threadIdx.x;
    if (i < n) atomicAdd(&deg[dst[i]], 1);
}

__global__ void scan_excl(const int* __restrict__ deg, int* __restrict__ rowptr, int n) {
    __shared__ int warp_sums[32];
    __shared__ int s_carry;
    int tid = threadIdx.x;          // 1024 threads
    int lane = tid & 31, wid = tid >> 5;
    if (tid == 0) s_carry = 0;
    __syncthreads();
    for (int base = 0; base < n; base += 1024) {
        int i = base + tid;
        int v = (i < n) ? deg[i] : 0;
        int x = v;
        #pragma unroll
        for (int off = 1; off < 32; off <<= 1) {
            int y = __shfl_up_sync(FULLMASK, x, off);
            if (lane >= off) x += y;
        }
        if (lane == 31) warp_sums[wid] = x;
        __syncthreads();
        if (tid < 32) {
            int s = warp_sums[tid];
            #pragma unroll
            for (int off = 1; off < 32; off <<= 1) {
                int y = __shfl_up_sync(FULLMASK, s, off);
                if (tid >= off) s += y;
            }
            warp_sums[tid] = s;
        }
        __syncthreads();
        int incl = x + (wid ? warp_sums[wid - 1] : 0);
        if (i < n) rowptr[i] = s_carry + incl - v;
        int chunk_total = warp_sums[31];
        __syncthreads();
        if (tid == 0) s_carry += chunk_total;
        __syncthreads();
    }
    if (tid == 0) rowptr[n] = s_carry;
}

__global__ void scatter_k(const int* __restrict__ src, const int* __restrict__ dst,
                          const int* __restrict__ rowptr, int* __restrict__ cur,
                          int* __restrict__ csr_src, int n) {
    int i = blockIdx.x * blockDim.x + threadIdx.x;
    if (i >= n) return;
    int d = dst[i];
    int pos = rowptr[d] + atomicAdd(&cur[d], 1);
    csr_src[pos] = src[i];
}

// ---------------- embed ----------------
__global__ void embed_k(const float* __restrict__ mass, const int* __restrict__ pstate,
                        const float* __restrict__ embW, const float* __restrict__ embS,
                        float* __restrict__ xp) {
    int idx = blockIdx.x * blockDim.x + threadIdx.x;
    if (idx >= NPC * 64) return;
    int n = idx >> 6, j = idx & 63;
    float v;
    if (j < 32) v = mass[n] * embW[j];
    else {
        int st = pstate[2 * n] + 2 * pstate[2 * n + 1];
        v = embS[st * 32 + (j - 32)];
    }
    xp[idx] = v;
}

// ---------------- score vectors for ALL layers: wsv[l,t] = Ws[l,t] @ a_s[l,t] ----------------
__global__ void vec_all(const float* __restrict__ Ws, const float* __restrict__ as,
                        const float* __restrict__ Wd, const float* __restrict__ ad,
                        float* __restrict__ wsv, float* __restrict__ wdv) {
    int idx = blockIdx.x * blockDim.x + threadIdx.x;   // 0..2559
    if (idx >= 2 * 5 * 4 * 64) return;
    int which = idx >= 1280;
    int r = which ? idx - 1280 : idx;
    int i = r & 63, lt = r >> 6;
    const float* W = which ? Wd : Ws;
    const float* a = which ? ad : as;
    float* o = which ? wdv : wsv;
    float acc = 0.f;
    const float* wr = W + (size_t)(lt * 64 + i) * 64;
    const float* ar = a + lt * 64;
    #pragma unroll 8
    for (int j = 0; j < 64; j++) acc = fmaf(wr[j], ar[j], acc);
    o[r] = acc;
}

// ---------------- up to 4 per-row dot products (layer-0 init only) ----------------
__global__ void dot4(const float* __restrict__ X, int n,
                     const float* v0, float* o0, const float* v1, float* o1,
                     const float* v2, float* o2, const float* v3, float* o3) {
    int idx = blockIdx.x * blockDim.x + threadIdx.x;
    int w = idx >> 5;
    if (w >= n) return;
    int lane = idx & 31;
    float2 x = *(const float2*)&X[(size_t)w * 64 + lane * 2];
#define DODOT(v, o) if (v) { \
        float s = x.x * v[2 * lane] + x.y * v[2 * lane + 1]; \
        for (int off = 16; off; off >>= 1) s += __shfl_xor_sync(FULLMASK, s, off); \
        if (lane == 0) o[w] = s; }
    DODOT(v0, o0)
    DODOT(v1, o1)
    DODOT(v2, o2)
    DODOT(v3, o3)
#undef DODOT
}

// ---------------- softmax weights per edge: thread per dst ----------------
__global__ void alpha_k(const int* __restrict__ rp, const int* __restrict__ cs,
                        const float* __restrict__ ss, const float* __restrict__ sd,
                        float* __restrict__ alpha, int n) {
    int d = blockIdx.x * blockDim.x + threadIdx.x;
    if (d >= n) return;
    int beg = rp[d], end = rp[d + 1];
    if (end <= beg) return;
    float sdv = sd[d];
    float m = -1e30f;
    #pragma unroll 4
    for (int j = beg; j < end; j++) {
        float e = ss[cs[j]] + sdv;
        e = e > 0.f ? e : 0.2f * e;
        m = fmaxf(m, e);
    }
    float s = 0.f;
    #pragma unroll 4
    for (int j = beg; j < end; j++) {
        float e = ss[cs[j]] + sdv;
        e = e > 0.f ? e : 0.2f * e;
        float ex = expf(e - m);
        alpha[j] = ex;
        s += ex;
    }
    float inv = 1.f / s;
    #pragma unroll 4
    for (int j = beg; j < end; j++) alpha[j] *= inv;
}

// ---------------- aggregation: z[d] = sum_j alpha_j * x[src_j]; warp per dst ----------------
__global__ void agg_k(const int* __restrict__ rp, const int* __restrict__ cs,
                      const float* __restrict__ alpha,
                      const float* __restrict__ X, float* __restrict__ Z, int n) {
    int idx = blockIdx.x * blockDim.x + threadIdx.x;
    int w = idx >> 5;
    if (w >= n) return;
    int lane = idx & 31;
    int beg = rp[w], end = rp[w + 1];
    float ax = 0.f, ay = 0.f;
    #pragma unroll 2
    for (int j = beg; j < end; j++) {
        float wt = alpha[j];        // warp-uniform broadcast load
        int s = cs[j];
        float2 h = *(const float2*)&X[(size_t)s * 64 + lane * 2];
        ax = fmaf(wt, h.x, ax);
        ay = fmaf(wt, h.y, ay);
    }
    *(float2*)&Z[(size_t)w * 64 + lane * 2] = make_float2(ax, ay);
}

// ---------------- fused matmul: Y = Z1@W1 (+ Z2@W2) + b1 (+b2), relu, epilogue dots ----------------
__global__ void mm_fused(const float* __restrict__ Z1, const float* __restrict__ W1,
                         const float* __restrict__ Z2, const float* __restrict__ W2,
                         const float* __restrict__ b1, const float* __restrict__ b2,
                         float* __restrict__ Y, int relu,
                         const float* v0, float* o0, const float* v1, float* o1,
                         const float* v2, float* o2, const float* v3, float* o3) {
    __shared__ float Xs[64][65];
    __shared__ float Wsh[64][68];
    int row0 = blockIdx.x * 64;
    int tid = threadIdx.x;      // 256
    int tx = tid & 15, ty = tid >> 4;
    int c0 = tx * 4, r0 = ty * 4;
    float acc[4][4] = {};
    for (int p = 0; p < 2; p++) {
        const float* Z = p ? Z2 : Z1;
        const float* W = p ? W2 : W1;
        if (!Z) break;
        const float4* W4 = (const float4*)W;
        for (int i = tid; i < 1024; i += 256) {
            float4 v = W4[i];
            int r = i >> 4, c = (i & 15) * 4;
            Wsh[r][c] = v.x; Wsh[r][c + 1] = v.y; Wsh[r][c + 2] = v.z; Wsh[r][c + 3] = v.w;
        }
        const float4* X4 = (const float4*)(Z + (size_t)row0 * 64);
        for (int i = tid; i < 1024; i += 256) {
            float4 v = X4[i];
            int r = i >> 4, c = (i & 15) * 4;
            Xs[r][c] = v.x; Xs[r][c + 1] = v.y; Xs[r][c + 2] = v.z; Xs[r][c + 3] = v.w;
        }
        __syncthreads();
        #pragma unroll
        for (int k = 0; k < 64; k++) {
            float4 w = *(const float4*)&Wsh[k][c0];
            float x0 = Xs[r0][k], x1 = Xs[r0 + 1][k], x2 = Xs[r0 + 2][k], x3 = Xs[r0 + 3][k];
            acc[0][0] = fmaf(x0, w.x, acc[0][0]); acc[0][1] = fmaf(x0, w.y, acc[0][1]);
            acc[0][2] = fmaf(x0, w.z, acc[0][2]); acc[0][3] = fmaf(x0, w.w, acc[0][3]);
            acc[1][0] = fmaf(x1, w.x, acc[1][0]); acc[1][1] = fmaf(x1, w.y, acc[1][1]);
            acc[1][2] = fmaf(x1, w.z, acc[1][2]); acc[1][3] = fmaf(x1, w.w, acc[1][3]);
            acc[2][0] = fmaf(x2, w.x, acc[2][0]); acc[2][1] = fmaf(x2, w.y, acc[2][1]);
            acc[2][2] = fmaf(x2, w.z, acc[2][2]); acc[2][3] = fmaf(x2, w.w, acc[2][3]);
            acc[3][0] = fmaf(x3, w.x, acc[3][0]); acc[3][1] = fmaf(x3, w.y, acc[3][1]);
            acc[3][2] = fmaf(x3, w.z, acc[3][2]); acc[3][3] = fmaf(x3, w.w, acc[3][3]);
        }
        __syncthreads();
    }
    // bias + relu
    float bv[4];
    #pragma unroll
    for (int c = 0; c < 4; c++) bv[c] = b1[c0 + c] + (b2 ? b2[c0 + c] : 0.f);
    #pragma unroll
    for (int i = 0; i < 4; i++)
        #pragma unroll
        for (int c = 0; c < 4; c++) {
            float v = acc[i][c] + bv[c];
            if (relu) v = fmaxf(v, 0.f);
            acc[i][c] = v;
        }
    #pragma unroll
    for (int i = 0; i < 4; i++) {
        float4 o = make_float4(acc[i][0], acc[i][1], acc[i][2], acc[i][3]);
        *(float4*)&Y[((size_t)(row0 + r0 + i)) * 64 + c0] = o;
    }
    // epilogue dots: o[row] = Y[row,:] . v
#define DOVEC(v, o) if (v) { \
        float vv0 = v[c0], vv1 = v[c0 + 1], vv2 = v[c0 + 2], vv3 = v[c0 + 3]; \
        _Pragma("unroll") \
        for (int i = 0; i < 4; i++) { \
            float part = acc[i][0] * vv0 + acc[i][1] * vv1 + acc[i][2] * vv2 + acc[i][3] * vv3; \
            for (int off = 8; off; off >>= 1) part += __shfl_xor_sync(FULLMASK, part, off); \
            if (tx == 0) o[row0 + r0 + i] = part; \
        } }
    DOVEC(v0, o0)
    DOVEC(v1, o1)
    DOVEC(v2, o2)
    DOVEC(v3, o3)
#undef DOVEC
}

// ---------------- pooling: max|min|mean per graph per dim ----------------
__global__ void pool_k(const float* __restrict__ x, int npg, float* __restrict__ rep, int off) {
    int b = blockIdx.x;
    int t = threadIdx.x;            // 256
    int d = t & 63, c = t >> 6;
    const float* base = x + (size_t)b * npg * 64;
    float mx = -1e30f, mn = 1e30f, sm = 0.f;
    for (int n = c; n < npg; n += 4) {
        float v = base[(size_t)n * 64 + d];
        mx = fmaxf(mx, v); mn = fminf(mn, v); sm += v;
    }
    __shared__ float smx[4][64], smn[4][64], ssm[4][64];
    smx[c][d] = mx; smn[c][d] = mn; ssm[c][d] = sm;
    __syncthreads();
    if (c == 0) {
        for (int i = 1; i < 4; i++) {
            mx = fmaxf(mx, smx[i][d]); mn = fminf(mn, smn[i][d]); sm += ssm[i][d];
        }
        rep[b * 576 + off + d] = mx;
        rep[b * 576 + off + 64 + d] = mn;
        rep[b * 576 + off + 128 + d] = sm / (float)npg;
    }
}

// ---------------- LayerNorm + out_a projection ----------------
__global__ void ln_ra(const float* __restrict__ ap, const float* __restrict__ g,
                      const float* __restrict__ be, const float* __restrict__ Wa,
                      const float* __restrict__ ba, float* __restrict__ ra) {
    int idx = blockIdx.x * blockDim.x + threadIdx.x;
    int n = idx >> 5;
    if (n >= NPC) return;
    int lane = idx & 31;
    float2 v = *(const float2*)&ap[(size_t)n * 64 + lane * 2];
    float sum = v.x + v.y;
    for (int o = 16; o; o >>= 1) sum += __shfl_xor_sync(FULLMASK, sum, o);
    float mu = sum * (1.f / 64.f);
    float dx = v.x - mu, dy = v.y - mu;
    float vs = dx * dx + dy * dy;
    for (int o = 16; o; o >>= 1) vs += __shfl_xor_sync(FULLMASK, vs, o);
    float rs = rsqrtf(vs * (1.f / 64.f) + 1e-5f);
    float y0 = dx * rs * g[2 * lane] + be[2 * lane];
    float y1 = dy * rs * g[2 * lane + 1] + be[2 * lane + 1];
    float r0 = y0 * Wa[(2 * lane) * 2]     + y1 * Wa[(2 * lane + 1) * 2];
    float r1 = y0 * Wa[(2 * lane) * 2 + 1] + y1 * Wa[(2 * lane + 1) * 2 + 1];
    for (int o = 16; o; o >>= 1) r0 += __shfl_xor_sync(FULLMASK, r0, o);
    for (int o = 16; o; o >>= 1) r1 += __shfl_xor_sync(FULLMASK, r1, o);
    if (lane == 0) {
        ra[2 * n]     = r0 + ba[0];
        ra[2 * n + 1] = r1 + ba[1];
    }
}

// ---------------- per-graph softmax + scatter to actions ----------------
__device__ __forceinline__ float blk64_max(float v, volatile float* sh) {
    for (int o = 16; o; o >>= 1) v = fmaxf(v, __shfl_xor_sync(FULLMASK, v, o));
    if ((threadIdx.x & 31) == 0) sh[threadIdx.x >> 5] = v;
    __syncthreads();
    float r = fmaxf(sh[0], sh[1]);
    __syncthreads();
    return r;
}
__device__ __forceinline__ float blk64_sum(float v, volatile float* sh) {
    for (int o = 16; o; o >>= 1) v += __shfl_xor_sync(FULLMASK, v, o);
    if ((threadIdx.x & 31) == 0) sh[threadIdx.x >> 5] = v;
    __syncthreads();
    float r = sh[0] + sh[1];
    __syncthreads();
    return r;
}

__global__ void act_softmax(const float* __restrict__ ra, const int* __restrict__ part_id,
                            float* __restrict__ out) {
    __shared__ float sh[2];
    int b = blockIdx.x, t = threadIdx.x;        // 64
    int n = b * 64 + t;
    float v0 = ra[2 * n], v1 = ra[2 * n + 1];
    float m0 = blk64_max(v0, sh);
    float m1 = blk64_max(v1, sh);
    float e0 = expf(v0 - m0), e1 = expf(v1 - m1);
    float s0 = blk64_sum(e0, sh);
    float s1 = blk64_sum(e1, sh);
    int p = part_id[n];
    out[b * 128 + p] = e0 / s0;
    out[b * 128 + 64 + p] = e1 / s1;
}

// ---------------- value head MLPs ----------------
__global__ void mlp_k(const float* __restrict__ in, int K, const float* __restrict__ W,
                      const float* __restrict__ bias, float* __restrict__ out) {
    __shared__ float s[576];
    int b = blockIdx.x, j = threadIdx.x;        // 64
    for (int k = j; k < K; k += 64) s[k] = in[b * K + k];
    __syncthreads();
    float acc = bias[j];
    for (int k = 0; k < K; k++) acc = fmaf(s[k], W[k * 64 + j], acc);
    acc = 0.5f * acc * (1.f + erff(acc * 0.70710678118654752f));
    out[b * 64 + j] = acc;
}

__global__ void mlp_out(const float* __restrict__ h, const float* __restrict__ Wo,
                        const float* __restrict__ bo, float* __restrict__ V) {
    int idx = blockIdx.x * blockDim.x + threadIdx.x;
    int b = idx >> 5;
    if (b >= BC) return;
    int lane = idx & 31;
    float2 v = *(const float2*)&h[b * 64 + lane * 2];
    float s = v.x * Wo[2 * lane] + v.y * Wo[2 * lane + 1];
    for (int o = 16; o; o >>= 1) s += __shfl_xor_sync(FULLMASK, s, o);
    if (lane == 0) V[b] = tanhf(s + bo[0]);
}

// ---------------- host ----------------
#define SYMF(p, s) do { void* _q; cudaGetSymbolAddress(&_q, s); p = (float*)_q; } while (0)
#define SYMI(p, s) do { void* _q; cudaGetSymbolAddress(&_q, s); p = (int*)_q; } while (0)

static void build_csr(const int* src, const int* dst, int n_dst, int* rowptr, int* csr_src, int* tmp) {
    int zb = (n_dst + 255) / 256;
    zero_i<<<zb, 256>>>(tmp, n_dst);
    hist_k<<<EC / 256, 256>>>(dst, tmp, EC);
    scan_excl<<<1, 1024>>>(tmp, rowptr, n_dst);
    zero_i<<<zb, 256>>>(tmp, n_dst);
    scatter_k<<<EC / 256, 256>>>(src, dst, rowptr, tmp, csr_src, EC);
}

extern "C" void kernel_launch(void* const* d_in, const int* in_sizes, int n_in,
                              void* d_out, int out_size) {
    const float* mass      = (const float*)d_in[0];
    const int*   pstate    = (const int*)d_in[1];
    const float* torque_x  = (const float*)d_in[2];
    const float* force_x   = (const float*)d_in[3];
    const int* e_pt_src = (const int*)d_in[4];
    const int* e_pt_dst = (const int*)d_in[5];
    const int* e_tp_src = (const int*)d_in[6];
    const int* e_tp_dst = (const int*)d_in[7];
    const int* e_pf_src = (const int*)d_in[8];
    const int* e_pf_dst = (const int*)d_in[9];
    const int* e_fp_src = (const int*)d_in[10];
    const int* e_fp_dst = (const int*)d_in[11];
    const int* part_id  = (const int*)d_in[13];
    const float* embW   = (const float*)d_in[14];
    const float* embS   = (const float*)d_in[15];
    const float* W_src  = (const float*)d_in[16];
    const float* a_src  = (const float*)d_in[18];
    const float* W_dst  = (const float*)d_in[17];
    const float* a_dst  = (const float*)d_in[19];
    const float* b_conv = (const float*)d_in[20];
    const float* ln_g   = (const float*)d_in[21];
    const float* ln_b   = (const float*)d_in[22];
    const float* outaW  = (const float*)d_in[23];
    const float* outab  = (const float*)d_in[24];
    const float* innW   = (const float*)d_in[25];
    const float* innb   = (const float*)d_in[26];
    const float* fulW   = (const float*)d_in[27];
    const float* fulb   = (const float*)d_in[28];
    const float* outW   = (const float*)d_in[29];
    const float* outb   = (const float*)d_in[30];
    float* out = (float*)d_out;

    float *xp, *xt, *xf, *ap, *zt, *zf, *ztp, *zfp;
    float *ss_pt, *ss_pf, *sd_tp, *sd_fp, *ss_tp, *sd_pt, *ss_fp, *sd_pf;
    float *a_pt, *a_tp, *a_pf, *a_fp, *wsv, *wdv, *ra, *rep, *h1, *h2;
    int *rp_pt, *rp_pf, *rp_tp, *rp_fp, *cs_pt, *cs_tp, *cs_pf, *cs_fp, *tmp;
    SYMF(xp, g_xp); SYMF(xt, g_xt); SYMF(xf, g_xf); SYMF(ap, g_ap);
    SYMF(zt, g_zt); SYMF(zf, g_zf); SYMF(ztp, g_ztp); SYMF(zfp, g_zfp);
    SYMF(ss_pt, g_ss_pt); SYMF(ss_pf, g_ss_pf); SYMF(sd_tp, g_sd_tp); SYMF(sd_fp, g_sd_fp);
    SYMF(ss_tp, g_ss_tp); SYMF(sd_pt, g_sd_pt); SYMF(ss_fp, g_ss_fp); SYMF(sd_pf, g_sd_pf);
    SYMF(a_pt, g_a_pt); SYMF(a_tp, g_a_tp); SYMF(a_pf, g_a_pf); SYMF(a_fp, g_a_fp);
    SYMF(wsv, g_wsv); SYMF(wdv, g_wdv); SYMF(ra, g_ra);
    SYMF(rep, g_rep); SYMF(h1, g_h1); SYMF(h2, g_h2);
    SYMI(rp_pt, g_rp_pt); SYMI(rp_pf, g_rp_pf); SYMI(rp_tp, g_rp_tp); SYMI(rp_fp, g_rp_fp);
    SYMI(cs_pt, g_cs_pt); SYMI(cs_tp, g_cs_tp); SYMI(cs_pf, g_cs_pf); SYMI(cs_fp, g_cs_fp);
    SYMI(tmp, g_tmp);

    // CSR per edge type (edges constant across layers)
    build_csr(e_pt_src, e_pt_dst, NTC, rp_pt, cs_pt, tmp);
    build_csr(e_tp_src, e_tp_dst, NPC, rp_tp, cs_tp, tmp);
    build_csr(e_pf_src, e_pf_dst, NFC, rp_pf, cs_pf, tmp);
    build_csr(e_fp_src, e_fp_dst, NPC, rp_fp, cs_fp, tmp);

    // score vectors for all layers; initial embed; layer-0 dots
    vec_all<<<10, 256>>>(W_src, a_src, W_dst, a_dst, wsv, wdv);
    embed_k<<<(NPC * 64) / 256, 256>>>(mass, pstate, embW, embS, xp);
    dot4<<<(NPC * 32) / 256, 256>>>(xp, NPC,
         wsv + 0 * 64, ss_pt, wsv + 2 * 64, ss_pf,
         wdv + 1 * 64, sd_tp, wdv + 3 * 64, sd_fp);
    dot4<<<(NTC * 32) / 256, 256>>>(torque_x, NTC,
         wsv + 1 * 64, ss_tp, wdv + 0 * 64, sd_pt, nullptr, nullptr, nullptr, nullptr);
    dot4<<<(NFC * 32) / 256, 256>>>(force_x, NFC,
         wsv + 3 * 64, ss_fp, wdv + 2 * 64, sd_pf, nullptr, nullptr, nullptr, nullptr);

    for (int l = 0; l < 5; l++) {
        const float* xpi = xp;
        const float* xti = (l == 0) ? torque_x : xt;
        const float* xfi = (l == 0) ? force_x : xf;
        const float* Wl = W_src + (size_t)l * 4 * 4096;
        const float* bl = b_conv + (size_t)l * 4 * 64;
        int relu = (l < 3) ? 1 : 0;
        int actor = (l == 4);
        const float* nwsv = wsv + (size_t)(l + 1) * 4 * 64;   // next layer's vectors
        const float* nwdv = wdv + (size_t)(l + 1) * 4 * 64;

        // edge softmax weights (current layer scores)
        if (!actor) {
            alpha_k<<<NTC / 256, 256>>>(rp_pt, cs_pt, ss_pt, sd_pt, a_pt, NTC);
            alpha_k<<<NFC / 256, 256>>>(rp_pf, cs_pf, ss_pf, sd_pf, a_pf, NFC);
        }
        alpha_k<<<NPC / 256, 256>>>(rp_tp, cs_tp, ss_tp, sd_tp, a_tp, NPC);
        alpha_k<<<NPC / 256, 256>>>(rp_fp, cs_fp, ss_fp, sd_fp, a_fp, NPC);

        // aggregation (gathers raw x)
        if (!actor) {
            agg_k<<<(NTC * 32) / 256, 256>>>(rp_pt, cs_pt, a_pt, xpi, zt, NTC);
            agg_k<<<(NFC * 32) / 256, 256>>>(rp_pf, cs_pf, a_pf, xpi, zf, NFC);
        }
        agg_k<<<(NPC * 32) / 256, 256>>>(rp_tp, cs_tp, a_tp, xti, ztp, NPC);
        agg_k<<<(NPC * 32) / 256, 256>>>(rp_fp, cs_fp, a_fp, xfi, zfp, NPC);

        // transform (+ bias + relu + next-layer attention dots in epilogue)
        if (!actor) {
            mm_fused<<<NTC / 64, 256>>>(zt, Wl + 0 * 4096, nullptr, nullptr,
                bl + 0 * 64, nullptr, xt, relu,
                nwsv + 1 * 64, ss_tp, nwdv + 0 * 64, sd_pt,
                nullptr, nullptr, nullptr, nullptr);
            mm_fused<<<NFC / 64, 256>>>(zf, Wl + 2 * 4096, nullptr, nullptr,
                bl + 2 * 64, nullptr, xf, relu,
                nwsv + 3 * 64, ss_fp, nwdv + 2 * 64, sd_pf,
                nullptr, nullptr, nullptr, nullptr);
            mm_fused<<<NPC / 64, 256>>>(ztp, Wl + 1 * 4096, zfp, Wl + 3 * 4096,
                bl + 1 * 64, bl + 3 * 64, xp, relu,
                nwsv + 0 * 64, ss_pt, nwsv + 2 * 64, ss_pf,
                nwdv + 1 * 64, sd_tp, nwdv + 3 * 64, sd_fp);
        } else {
            mm_fused<<<NPC / 64, 256>>>(ztp, Wl + 1 * 4096, zfp, Wl + 3 * 4096,
                bl + 1 * 64, bl + 3 * 64, ap, 0,
                nullptr, nullptr, nullptr, nullptr,
                nullptr, nullptr, nullptr, nullptr);
        }
    }

    // pooling over x(4) (xp/xt/xf untouched by actor layer outputs)
    pool_k<<<BC, 256>>>(xp, 64, rep, 0);
    pool_k<<<BC, 256>>>(xt, 512, rep, 192);
    pool_k<<<BC, 256>>>(xf, 512, rep, 384);

    // actor head
    ln_ra<<<(NPC * 32) / 256, 256>>>(ap, ln_g, ln_b, outaW, outab, ra);
    act_softmax<<<BC, 64>>>(ra, part_id, out);

    // value head
    mlp_k<<<BC, 64>>>(rep, 576, innW, innb, h1);
    mlp_k<<<BC, 64>>>(h1, 64, fulW, fulb, h2);
    mlp_out<<<(BC * 32) / 256, 256>>>(h2, outW, outb, out + BC * 128);
}